// round 10
// baseline (speedup 1.0000x reference)
#include <cuda_runtime.h>
#include <math.h>
#include <stdint.h>

#define T_LEN        32768
#define B_SEG        8
#define H_HEADS      8
#define C_COLS       1024
#define C4           256
#define RBLK         1024
#define ROWS_PER_BLK 32
#define NCTA         16            // MLP CTAs (j-split 16)
#define NTHR         512

// ---------------- device scratch (zero-initialized at module load) -----------
__device__ float g_accum[B_SEG * C_COLS];   // segment sums; invariant: 0 at entry
__device__ float g_h1[B_SEG * 1024];
__device__ float g_h2[B_SEG * 256];
__device__ float g_h3[B_SEG * 512];
__device__ float g_h4[B_SEG * 128];
__device__ unsigned          g_cnt[6];
__device__ volatile unsigned g_gen[6];

__device__ __forceinline__ float silu(float v) { return v / (1.0f + expf(-v)); }

__device__ __forceinline__ void grid_bar(int id, unsigned target, bool wait)
{
    __syncthreads();
    if (threadIdx.x == 0) {
        __threadfence();
        unsigned gen = g_gen[id];
        if (atomicAdd(&g_cnt[id], 1u) == target - 1u) {
            g_cnt[id] = 0u;
            __threadfence();
            g_gen[id] = gen + 1u;
        } else if (wait) {
            while (g_gen[id] == gen) __nanosleep(32);
            __threadfence();
        }
    }
    __syncthreads();
}

// =================== K1: streaming segment-sum (unchanged) ====================
__global__ void __launch_bounds__(256) reduce_kernel(
    const float4* __restrict__ x4, const int* __restrict__ cu)
{
    const int tid = threadIdx.x;
    const int t0  = blockIdx.x * ROWS_PER_BLK;

    __shared__ int scu[B_SEG + 1];
    if (tid <= B_SEG) scu[tid] = cu[tid];
    __syncthreads();

    const int t1 = t0 + ROWS_PER_BLK - 1;
    int s0 = 0; while (s0 < B_SEG - 1 && t0 >= scu[s0 + 1]) s0++;
    int s1 = 0; while (s1 < B_SEG - 1 && t1 >= scu[s1 + 1]) s1++;

    const float4* xp = x4 + (size_t)t0 * C4 + tid;

    if (s0 == s1) {
        float4 a[8];
        #pragma unroll
        for (int i = 0; i < 8; i++) a[i] = make_float4(0.f,0.f,0.f,0.f);
        #pragma unroll
        for (int r = 0; r < ROWS_PER_BLK; r += 8) {
            #pragma unroll
            for (int u = 0; u < 8; u++) {
                float4 v = __ldcs(&xp[(r + u) * C4]);
                a[u].x += v.x; a[u].y += v.y; a[u].z += v.z; a[u].w += v.w;
            }
        }
        #pragma unroll
        for (int s = 4; s > 0; s >>= 1)
            #pragma unroll
            for (int i = 0; i < s; i++) {
                a[i].x += a[i+s].x; a[i].y += a[i+s].y;
                a[i].z += a[i+s].z; a[i].w += a[i+s].w;
            }
        float* dst = g_accum + s0 * C_COLS + tid * 4;
        atomicAdd(dst + 0, a[0].x); atomicAdd(dst + 1, a[0].y);
        atomicAdd(dst + 2, a[0].z); atomicAdd(dst + 3, a[0].w);
    } else {
        float4 a = make_float4(0.f,0.f,0.f,0.f);
        int seg = s0;
        int nxt = (seg < B_SEG - 1) ? scu[seg + 1] : 0x7fffffff;
        for (int r = 0; r < ROWS_PER_BLK; r++) {
            int t = t0 + r;
            if (t >= nxt) {
                float* dst = g_accum + seg * C_COLS + tid * 4;
                atomicAdd(dst + 0, a.x); atomicAdd(dst + 1, a.y);
                atomicAdd(dst + 2, a.z); atomicAdd(dst + 3, a.w);
                a = make_float4(0.f,0.f,0.f,0.f);
                while (seg < B_SEG - 1 && t >= scu[seg + 1]) seg++;
                nxt = (seg < B_SEG - 1) ? scu[seg + 1] : 0x7fffffff;
            }
            float4 v = __ldcs(&xp[r * C4]);
            a.x += v.x; a.y += v.y; a.z += v.z; a.w += v.w;
        }
        float* dst = g_accum + seg * C_COLS + tid * 4;
        atomicAdd(dst + 0, a.x); atomicAdd(dst + 1, a.y);
        atomicAdd(dst + 2, a.z); atomicAdd(dst + 3, a.w);
    }
}

// =================== async-copy helpers =======================================
__device__ __forceinline__ uint32_t smem_u32(const void* p) {
    uint32_t a;
    asm("{ .reg .u64 t; cvta.to.shared.u64 t, %1; cvt.u32.u64 %0, t; }"
        : "=r"(a) : "l"(p));
    return a;
}
__device__ __forceinline__ void cp_async16(uint32_t dst, const void* src) {
    asm volatile("cp.async.cg.shared.global [%0], [%1], 16;"
                 :: "r"(dst), "l"(src) : "memory");
}
__device__ __forceinline__ void cp_commit() {
    asm volatile("cp.async.commit_group;" ::: "memory");
}
template<int N> __device__ __forceinline__ void cp_wait() {
    asm volatile("cp.async.wait_group %0;" :: "n"(N) : "memory");
}

// ---- smem layout (floats, dynamic) -------------------------------------------
// ws1 [128 x 64]   @ 0        8192
// ws2 [1024 x 16]  @ 8192    16384
// ws3 [256 x 32]   @ 24576    8192
// ws4 [512 x 8]    @ 32768    4096
// xs  [8 x (K+4)]  @ 36864    8224   (activations, stride K+4 per batch)
// red [512 float4] @ 45088    2048
// l0/l1            @ 47136     256
#define SM_W1   0
#define SM_W2   8192
#define SM_W3   24576
#define SM_W4   32768
#define SM_XS   36864
#define SM_RED  45088
#define SM_L0   47136
#define SM_L1V  47264
#define SM_TOT  47392          // floats -> 189,568 bytes

// preload a layer's weight slice [K x SLICE] into smem via cp.async
template<int K, int N, int SLICE>
__device__ __forceinline__ void preload(const float* __restrict__ W, int rank,
                                        int tid, uint32_t dst_u32)
{
    constexpr int CROW = SLICE / 4;                // 16B chunks per row
    constexpr int CPT  = (K * SLICE / 4) / NTHR;   // chunks per thread
    const float* wg = W + rank * SLICE;
    #pragma unroll
    for (int c = 0; c < CPT; c++) {
        int chunk = c * NTHR + tid;
        int row   = chunk / CROW;
        int col   = chunk - row * CROW;
        cp_async16(dst_u32 + (uint32_t)(row * SLICE + col * 4) * 4u,
                   wg + (size_t)row * N + col * 4);
    }
    cp_commit();
}

// gather full activation [8 x K] from global into xs (stride K+4)
template<int K>
__device__ __forceinline__ void gather(const float* __restrict__ gin,
                                       float* __restrict__ xs, int tid)
{
    constexpr int CPT = (K * 8 / 4) / NTHR;
    #pragma unroll
    for (int c = 0; c < CPT; c++) {
        int chunk = c * NTHR + tid;
        int j4 = chunk & (K / 4 - 1);
        int b  = chunk / (K / 4);
        float4 v = __ldcg((const float4*)&gin[b * K + j4 * 4]);
        *(float4*)&xs[b * (K + 4) + j4 * 4] = v;
    }
    __syncthreads();
}

// compute one layer from smem weights; write slice to global
template<int K, int N, int SLICE, int NKS, bool ACT>
__device__ __forceinline__ void do_layer(
    const float* __restrict__ wsm, const float* __restrict__ Bv,
    const float* __restrict__ xs, float4* __restrict__ red,
    float* __restrict__ gout, int rank, int tid)
{
    constexpr int NJ4  = SLICE / 4;
    constexpr int KLEN = K / NKS;
    const int j4   = tid % NJ4;
    const int rest = tid / NJ4;
    const int b    = rest & 7;
    const int ks   = rest >> 3;
    const int k0   = ks * KLEN;

    const float* xb = xs + b * (K + 4);
    float4 acc = make_float4(0.f, 0.f, 0.f, 0.f);
    #pragma unroll 8
    for (int k = k0; k < k0 + KLEN; k++) {
        float4 w = *(const float4*)&wsm[k * SLICE + j4 * 4];
        float  x = xb[k];
        acc.x += x * w.x; acc.y += x * w.y;
        acc.z += x * w.z; acc.w += x * w.w;
    }
    red[(ks * 8 + b) * NJ4 + j4] = acc;
    __syncthreads();

    if (tid < NJ4 * 8) {
        const int oj = tid % NJ4, ob = tid / NJ4;
        float4 s = make_float4(0.f, 0.f, 0.f, 0.f);
        #pragma unroll
        for (int q = 0; q < NKS; q++) {
            float4 v = red[(q * 8 + ob) * NJ4 + oj];
            s.x += v.x; s.y += v.y; s.z += v.z; s.w += v.w;
        }
        float4 bias = *(const float4*)&Bv[rank * SLICE + oj * 4];
        float4 o;
        if (ACT) {
            o.x = silu(s.x + bias.x); o.y = silu(s.y + bias.y);
            o.z = silu(s.z + bias.z); o.w = silu(s.w + bias.w);
        } else {
            o.x = s.x + bias.x; o.y = s.y + bias.y;
            o.z = s.z + bias.z; o.w = s.w + bias.w;
        }
        *(float4*)&gout[ob * N + rank * SLICE + oj * 4] = o;
    }
}

// =================== K2: smem-resident-weight MLP ==============================
// 16 CTAs x 512 threads; CTA owns 1/16 of every layer's outputs, all 8 batches.
__global__ void __launch_bounds__(NTHR) mlp_kernel(
    const int* __restrict__ cu,
    const float* __restrict__ w1, const float* __restrict__ b1,
    const float* __restrict__ w2, const float* __restrict__ b2,
    const float* __restrict__ w3, const float* __restrict__ b3,
    const float* __restrict__ w4, const float* __restrict__ b4,
    const float* __restrict__ w5, const float* __restrict__ b5,
    float* __restrict__ out)
{
    extern __shared__ float sm[];
    float*  ws1 = sm + SM_W1;
    float*  ws2 = sm + SM_W2;
    float*  ws3 = sm + SM_W3;
    float*  ws4 = sm + SM_W4;
    float*  xs  = sm + SM_XS;
    float4* red = (float4*)(sm + SM_RED);
    float*  l0  = sm + SM_L0;
    float*  l1  = sm + SM_L1V;

    const int tid  = threadIdx.x;
    const int rank = blockIdx.x;
    const uint32_t sm0 = smem_u32(sm);

    // ---- fire-and-forget weight preload (4 groups, newest-first pending) -----
    preload< 128, 1024,  64>(w1, rank, tid, sm0 + SM_W1 * 4u);
    preload<1024,  256,  16>(w2, rank, tid, sm0 + SM_W2 * 4u);
    preload< 256,  512,  32>(w3, rank, tid, sm0 + SM_W3 * 4u);
    preload< 512,  128,   8>(w4, rank, tid, sm0 + SM_W4 * 4u);

    // ---- pooled mean (overlaps with weight copies) ----------------------------
    {
        #pragma unroll
        for (int c = 0; c < 2; c++) {
            int i = c * NTHR + tid;            // i = b*128 + k
            int k = i & 127, b = i >> 7;
            float s = 0.f;
            #pragma unroll
            for (int h = 0; h < H_HEADS; h++)
                s += __ldcg(&g_accum[b * C_COLS + h * 128 + k]);
            int cnt = cu[b + 1] - cu[b];
            if (cnt < 1) cnt = 1;
            xs[b * 132 + k] = s / ((float)cnt * (float)H_HEADS);
        }
    }
    cp_wait<3>();                               // L1 weights resident
    __syncthreads();

    // ---- L1: 128 -> 1024, silu. SLICE=64, NKS=4 -------------------------------
    do_layer< 128, 1024, 64,  4, true >(ws1, b1, xs, red, g_h1, rank, tid);
    grid_bar(1, NCTA, true);

    // reset segment accumulator (fully consumed above)
    g_accum[rank * 512 + tid] = 0.f;

    // ---- L2: 1024 -> 256, no act. SLICE=16, NKS=16 ----------------------------
    gather<1024>(g_h1, xs, tid);
    cp_wait<2>();
    __syncthreads();
    do_layer<1024,  256, 16, 16, false>(ws2, b2, xs, red, g_h2, rank, tid);
    grid_bar(2, NCTA, true);

    // ---- L3: 256 -> 512, silu. SLICE=32, NKS=8 --------------------------------
    gather< 256>(g_h2, xs, tid);
    cp_wait<1>();
    __syncthreads();
    do_layer< 256,  512, 32,  8, true >(ws3, b3, xs, red, g_h3, rank, tid);
    grid_bar(3, NCTA, true);

    // ---- L4: 512 -> 128, silu. SLICE=8, NKS=32 --------------------------------
    gather< 512>(g_h3, xs, tid);
    cp_wait<0>();
    __syncthreads();
    do_layer< 512,  128,  8, 32, true >(ws4, b4, xs, red, g_h4, rank, tid);
    grid_bar(4, NCTA, rank < 8);
    if (rank >= 8) return;

    // ---- L5: 128 -> 2, argmax, output (CTA rank = batch) -----------------------
    {
        const int b = rank;
        if (tid < 128) {
            float v = __ldcg(&g_h4[b * 128 + tid]);
            l0[tid] = v * w5[tid * 2 + 0];
            l1[tid] = v * w5[tid * 2 + 1];
        }
        __syncthreads();
        #pragma unroll
        for (int stride = 64; stride > 0; stride >>= 1) {
            if (tid < stride) {
                l0[tid] += l0[tid + stride];
                l1[tid] += l1[tid + stride];
            }
            __syncthreads();
        }
        if (tid == 0) {
            float lg0 = l0[0] + b5[0];
            float lg1 = l1[0] + b5[1];
            float z = (lg1 > lg0) ? 1.0f : 0.0f;   // argmax; tie -> class 0
            #pragma unroll
            for (int h = 0; h < H_HEADS; h++)
                out[b * H_HEADS + h] = z;
        }
    }
}

// ---------------- launch --------------------------------------------------------
extern "C" void kernel_launch(void* const* d_in, const int* in_sizes, int n_in,
                              void* d_out, int out_size)
{
    const float* x  = (const float*)d_in[0];
    const int*   cu = (const int*)  d_in[1];
    const float* w1 = (const float*)d_in[2];
    const float* b1 = (const float*)d_in[3];
    const float* w2 = (const float*)d_in[4];
    const float* b2 = (const float*)d_in[5];
    const float* w3 = (const float*)d_in[6];
    const float* b3 = (const float*)d_in[7];
    const float* w4 = (const float*)d_in[8];
    const float* b4 = (const float*)d_in[9];
    const float* w5 = (const float*)d_in[10];
    const float* b5 = (const float*)d_in[11];

    static int smem_set = 0;
    if (!smem_set) {
        cudaFuncSetAttribute(mlp_kernel,
                             cudaFuncAttributeMaxDynamicSharedMemorySize,
                             SM_TOT * 4);
        smem_set = 1;
    }

    reduce_kernel<<<RBLK, 256>>>((const float4*)x, cu);
    mlp_kernel<<<NCTA, NTHR, SM_TOT * 4>>>(cu, w1, b1, w2, b2, w3, b3,
                                           w4, b4, w5, b5, (float*)d_out);
}

// round 11
// speedup vs baseline: 1.0641x; 1.0641x over previous
#include <cuda_runtime.h>
#include <math.h>
#include <stdint.h>

#define T_LEN        32768
#define B_SEG        8
#define H_HEADS      8
#define C_COLS       1024
#define C4           256
#define RBLK         1024
#define ROWS_PER_BLK 32
#define NCTA         16
#define NTHR         512

// ---------------- device scratch (zero-initialized at module load) -----------
__device__ float g_accum[B_SEG * C_COLS];  // segment sums; 0 at entry
__device__ float g_h2[B_SEG * 256];        // L2 partial sums;   0 at entry
__device__ float g_h4[B_SEG * 128];        // L4 partial sums;   0 at entry
__device__ unsigned          g_cnt[4];
__device__ volatile unsigned g_gen[4];

__device__ __forceinline__ float silu(float v) { return v / (1.0f + expf(-v)); }

// busy-poll grid barrier (no nanosleep); generation monotonic across replays
__device__ __forceinline__ void grid_bar(int id, unsigned target)
{
    __syncthreads();
    if (threadIdx.x == 0) {
        __threadfence();
        unsigned gen = g_gen[id];
        if (atomicAdd(&g_cnt[id], 1u) == target - 1u) {
            g_cnt[id] = 0u;
            __threadfence();
            g_gen[id] = gen + 1u;
        } else {
            while (g_gen[id] == gen) { }
            __threadfence();
        }
    }
    __syncthreads();
}

// =================== K1: streaming segment-sum (unchanged) ====================
__global__ void __launch_bounds__(256) reduce_kernel(
    const float4* __restrict__ x4, const int* __restrict__ cu)
{
    const int tid = threadIdx.x;
    const int t0  = blockIdx.x * ROWS_PER_BLK;

    __shared__ int scu[B_SEG + 1];
    if (tid <= B_SEG) scu[tid] = cu[tid];
    __syncthreads();

    const int t1 = t0 + ROWS_PER_BLK - 1;
    int s0 = 0; while (s0 < B_SEG - 1 && t0 >= scu[s0 + 1]) s0++;
    int s1 = 0; while (s1 < B_SEG - 1 && t1 >= scu[s1 + 1]) s1++;

    const float4* xp = x4 + (size_t)t0 * C4 + tid;

    if (s0 == s1) {
        float4 a[8];
        #pragma unroll
        for (int i = 0; i < 8; i++) a[i] = make_float4(0.f,0.f,0.f,0.f);
        #pragma unroll
        for (int r = 0; r < ROWS_PER_BLK; r += 8) {
            #pragma unroll
            for (int u = 0; u < 8; u++) {
                float4 v = __ldcs(&xp[(r + u) * C4]);
                a[u].x += v.x; a[u].y += v.y; a[u].z += v.z; a[u].w += v.w;
            }
        }
        #pragma unroll
        for (int s = 4; s > 0; s >>= 1)
            #pragma unroll
            for (int i = 0; i < s; i++) {
                a[i].x += a[i+s].x; a[i].y += a[i+s].y;
                a[i].z += a[i+s].z; a[i].w += a[i+s].w;
            }
        float* dst = g_accum + s0 * C_COLS + tid * 4;
        atomicAdd(dst + 0, a[0].x); atomicAdd(dst + 1, a[0].y);
        atomicAdd(dst + 2, a[0].z); atomicAdd(dst + 3, a[0].w);
    } else {
        float4 a = make_float4(0.f,0.f,0.f,0.f);
        int seg = s0;
        int nxt = (seg < B_SEG - 1) ? scu[seg + 1] : 0x7fffffff;
        for (int r = 0; r < ROWS_PER_BLK; r++) {
            int t = t0 + r;
            if (t >= nxt) {
                float* dst = g_accum + seg * C_COLS + tid * 4;
                atomicAdd(dst + 0, a.x); atomicAdd(dst + 1, a.y);
                atomicAdd(dst + 2, a.z); atomicAdd(dst + 3, a.w);
                a = make_float4(0.f,0.f,0.f,0.f);
                while (seg < B_SEG - 1 && t >= scu[seg + 1]) seg++;
                nxt = (seg < B_SEG - 1) ? scu[seg + 1] : 0x7fffffff;
            }
            float4 v = __ldcs(&xp[r * C4]);
            a.x += v.x; a.y += v.y; a.z += v.z; a.w += v.w;
        }
        float* dst = g_accum + seg * C_COLS + tid * 4;
        atomicAdd(dst + 0, a.x); atomicAdd(dst + 1, a.y);
        atomicAdd(dst + 2, a.z); atomicAdd(dst + 3, a.w);
    }
}

// =================== async-copy helpers =======================================
__device__ __forceinline__ uint32_t smem_u32(const void* p) {
    uint32_t a;
    asm("{ .reg .u64 t; cvta.to.shared.u64 t, %1; cvt.u32.u64 %0, t; }"
        : "=r"(a) : "l"(p));
    return a;
}
__device__ __forceinline__ void cp_async16(uint32_t dst, const void* src) {
    asm volatile("cp.async.cg.shared.global [%0], [%1], 16;"
                 :: "r"(dst), "l"(src) : "memory");
}
__device__ __forceinline__ void cp_commit() {
    asm volatile("cp.async.commit_group;" ::: "memory");
}
template<int N> __device__ __forceinline__ void cp_wait() {
    asm volatile("cp.async.wait_group %0;" :: "n"(N) : "memory");
}

// ---- smem layout (floats) ----------------------------------------------------
// ws1 [128 x 64]  @     0   8192   (w1 column slice)
// ws2 [64 x 256]  @  8192  16384   (w2 row slice, contiguous)
// ws3 [256 x 32]  @ 24576   8192   (w3 column slice)
// ws4 [32 x 128]  @ 32768   4096   (w4 row slice, contiguous)
// xs0 [8 x 260]   @ 36864   2080   (pooled / h2)
// xs1 [8 x 68|36] @ 38944    544   (h1 local / h3 local)
// red [512 f4]    @ 39488   2048
// l0,l1           @ 41536    256
#define SM_W1   0
#define SM_W2   8192
#define SM_W3   24576
#define SM_W4   32768
#define SM_XS0  36864
#define SM_XS1  38944
#define SM_RED  39488
#define SM_L0   41536
#define SM_L1V  41664
#define SM_TOT  41792          // floats -> 167,168 bytes

// column-slice preload: [K rows x SLICE cols] from W (row stride N)
template<int K, int N, int SLICE>
__device__ __forceinline__ void preload_cols(const float* __restrict__ W,
                                             int rank, int tid, uint32_t dst)
{
    constexpr int CROW = SLICE / 4;
    constexpr int CPT  = (K * SLICE / 4) / NTHR;
    const float* wg = W + rank * SLICE;
    #pragma unroll
    for (int c = 0; c < CPT; c++) {
        int chunk = c * NTHR + tid;
        int row   = chunk / CROW;
        int col   = chunk - row * CROW;
        cp_async16(dst + (uint32_t)(row * SLICE + col * 4) * 4u,
                   wg + (size_t)row * N + col * 4);
    }
    cp_commit();
}
// contiguous row-slice preload: FLOATS floats starting at W + rank*FLOATS
template<int FLOATS>
__device__ __forceinline__ void preload_rows(const float* __restrict__ W,
                                             int rank, int tid, uint32_t dst)
{
    constexpr int CPT = (FLOATS / 4) / NTHR;
    const float* wg = W + (size_t)rank * FLOATS;
    #pragma unroll
    for (int c = 0; c < CPT; c++) {
        int chunk = c * NTHR + tid;
        cp_async16(dst + (uint32_t)chunk * 16u, wg + chunk * 4);
    }
    cp_commit();
}

// =================== K2: 2-barrier MLP =========================================
__global__ void __launch_bounds__(NTHR) mlp_kernel(
    const int* __restrict__ cu,
    const float* __restrict__ w1, const float* __restrict__ b1,
    const float* __restrict__ w2, const float* __restrict__ b2,
    const float* __restrict__ w3, const float* __restrict__ b3,
    const float* __restrict__ w4, const float* __restrict__ b4,
    const float* __restrict__ w5, const float* __restrict__ b5,
    float* __restrict__ out)
{
    extern __shared__ float sm[];
    float*  ws1 = sm + SM_W1;
    float*  ws2 = sm + SM_W2;
    float*  ws3 = sm + SM_W3;
    float*  ws4 = sm + SM_W4;
    float*  xs0 = sm + SM_XS0;
    float*  xs1 = sm + SM_XS1;
    float4* red = (float4*)(sm + SM_RED);
    float*  l0  = sm + SM_L0;
    float*  l1  = sm + SM_L1V;

    const int tid  = threadIdx.x;
    const int rank = blockIdx.x;
    const uint32_t sm0 = smem_u32(sm);

    // ---- weight preload: 4 groups, fire-and-forget ---------------------------
    preload_cols<128, 1024, 64>(w1, rank, tid, sm0 + SM_W1 * 4u);
    preload_rows<64 * 256>     (w2, rank, tid, sm0 + SM_W2 * 4u);
    preload_cols<256,  512, 32>(w3, rank, tid, sm0 + SM_W3 * 4u);
    preload_rows<32 * 128>     (w4, rank, tid, sm0 + SM_W4 * 4u);

    // ---- pooled mean (overlaps with copies) ----------------------------------
    #pragma unroll
    for (int c = 0; c < 2; c++) {
        int i = c * NTHR + tid;            // i = b*128 + k
        int k = i & 127, b = i >> 7;
        float s = 0.f;
        #pragma unroll
        for (int h = 0; h < H_HEADS; h++)
            s += __ldcg(&g_accum[b * C_COLS + h * 128 + k]);
        int cnt = cu[b + 1] - cu[b];
        if (cnt < 1) cnt = 1;
        xs0[b * 260 + k] = s / ((float)cnt * (float)H_HEADS);
    }
    cp_wait<3>();                           // ws1 resident
    __syncthreads();

    // ---- L1: 128 -> [64-slice], silu, LOCAL. 16 j4 x 8 b x 4 ks (k=32) -------
    {
        const int j4 = tid & 15, b = (tid >> 4) & 7, ks = tid >> 7;
        const int k0 = ks * 32;
        float4 acc = make_float4(0.f,0.f,0.f,0.f);
        const float* xb = xs0 + b * 260;
        #pragma unroll 8
        for (int k = k0; k < k0 + 32; k++) {
            float4 w = *(const float4*)&ws1[k * 64 + j4 * 4];
            float  x = xb[k];
            acc.x += x * w.x; acc.y += x * w.y;
            acc.z += x * w.z; acc.w += x * w.w;
        }
        red[(b * 16 + j4) * 4 + ks] = acc;
        __syncthreads();
        if (tid < 128) {
            const int ob = tid >> 4, oj = tid & 15;
            float4 s = make_float4(0.f,0.f,0.f,0.f);
            #pragma unroll
            for (int q = 0; q < 4; q++) {
                float4 v = red[(ob * 16 + oj) * 4 + q];
                s.x += v.x; s.y += v.y; s.z += v.z; s.w += v.w;
            }
            float4 bias = *(const float4*)&b1[rank * 64 + oj * 4];
            float4 o;
            o.x = silu(s.x + bias.x); o.y = silu(s.y + bias.y);
            o.z = silu(s.z + bias.z); o.w = silu(s.w + bias.w);
            *(float4*)&xs1[ob * 68 + oj * 4] = o;
        }
    }
    cp_wait<2>();                           // ws2 resident
    __syncthreads();

    // ---- L2 partial: own 64 k-rows x all 256 j x 8 b -> RED into g_h2 --------
    {
        const int j4 = tid & 63, b = tid >> 6;
        float4 acc = make_float4(0.f,0.f,0.f,0.f);
        const float* xb = xs1 + b * 68;
        #pragma unroll 8
        for (int k = 0; k < 64; k++) {
            float4 w = *(const float4*)&ws2[k * 256 + j4 * 4];
            float  x = xb[k];
            acc.x += x * w.x; acc.y += x * w.y;
            acc.z += x * w.z; acc.w += x * w.w;
        }
        float* dst = &g_h2[b * 256 + j4 * 4];
        atomicAdd(dst + 0, acc.x); atomicAdd(dst + 1, acc.y);
        atomicAdd(dst + 2, acc.z); atomicAdd(dst + 3, acc.w);
    }
    grid_bar(1, NCTA);

    // reset segment accumulator (pooled reads all done before bar1)
    g_accum[rank * 512 + tid] = 0.f;

    // ---- gather h2 (+bias) : one float4 per thread ----------------------------
    {
        const int j4 = tid & 63, b = tid >> 6;
        float4 v = __ldcg((const float4*)&g_h2[b * 256 + j4 * 4]);
        float4 bias = *(const float4*)&b2[j4 * 4];
        v.x += bias.x; v.y += bias.y; v.z += bias.z; v.w += bias.w;
        *(float4*)&xs0[b * 260 + j4 * 4] = v;
    }
    cp_wait<1>();                           // ws3 resident
    __syncthreads();

    // ---- L3: 256 -> [32-slice], silu, LOCAL. 8 j4 x 8 b x 8 ks (k=32) ---------
    {
        const int j4 = tid & 7, b = (tid >> 3) & 7, ks = tid >> 6;
        const int k0 = ks * 32;
        float4 acc = make_float4(0.f,0.f,0.f,0.f);
        const float* xb = xs0 + b * 260;
        #pragma unroll 8
        for (int k = k0; k < k0 + 32; k++) {
            float4 w = *(const float4*)&ws3[k * 32 + j4 * 4];
            float  x = xb[k];
            acc.x += x * w.x; acc.y += x * w.y;
            acc.z += x * w.z; acc.w += x * w.w;
        }
        red[(b * 8 + j4) * 8 + ks] = acc;
        __syncthreads();
        if (tid < 64) {
            const int ob = tid >> 3, oj = tid & 7;
            float4 s = make_float4(0.f,0.f,0.f,0.f);
            #pragma unroll
            for (int q = 0; q < 8; q++) {
                float4 v = red[(ob * 8 + oj) * 8 + q];
                s.x += v.x; s.y += v.y; s.z += v.z; s.w += v.w;
            }
            float4 bias = *(const float4*)&b3[rank * 32 + oj * 4];
            float4 o;
            o.x = silu(s.x + bias.x); o.y = silu(s.y + bias.y);
            o.z = silu(s.z + bias.z); o.w = silu(s.w + bias.w);
            *(float4*)&xs1[ob * 36 + oj * 4] = o;
        }
    }
    cp_wait<0>();                           // ws4 resident
    __syncthreads();

    // ---- L4 partial: own 32 k-rows x all 128 j x 8 b -> RED into g_h4 ---------
    {
        const int j4 = tid & 31, b = (tid >> 5) & 7, ks = tid >> 8;
        const int k0 = ks * 16;
        float4 acc = make_float4(0.f,0.f,0.f,0.f);
        const float* xb = xs1 + b * 36;
        #pragma unroll 8
        for (int k = k0; k < k0 + 16; k++) {
            float4 w = *(const float4*)&ws4[k * 128 + j4 * 4];
            float  x = xb[k];
            acc.x += x * w.x; acc.y += x * w.y;
            acc.z += x * w.z; acc.w += x * w.w;
        }
        red[(b * 32 + j4) * 2 + ks] = acc;
        __syncthreads();
        if (tid < 256) {
            const int ob = tid >> 5, oj = tid & 31;
            float4 s0 = red[(ob * 32 + oj) * 2 + 0];
            float4 s1 = red[(ob * 32 + oj) * 2 + 1];
            float* dst = &g_h4[ob * 128 + oj * 4];
            atomicAdd(dst + 0, s0.x + s1.x); atomicAdd(dst + 1, s0.y + s1.y);
            atomicAdd(dst + 2, s0.z + s1.z); atomicAdd(dst + 3, s0.w + s1.w);
        }
    }
    grid_bar(2, NCTA);

    // reset h2 partials for next replay (all gathers happened before bar2)
    if (tid < 128) g_h2[rank * 128 + tid] = 0.f;
    if (rank >= 8) return;

    // ---- L5: batch = rank. silu(h4)+dot w5, argmax, out, reset ----------------
    {
        const int b = rank;
        if (tid < 128) {
            float v = silu(__ldcg(&g_h4[b * 128 + tid]) + b4[tid]);
            l0[tid] = v * w5[tid * 2 + 0];
            l1[tid] = v * w5[tid * 2 + 1];
            g_h4[b * 128 + tid] = 0.f;        // same-thread reset after read
        }
        __syncthreads();
        #pragma unroll
        for (int stride = 64; stride > 0; stride >>= 1) {
            if (tid < stride) {
                l0[tid] += l0[tid + stride];
                l1[tid] += l1[tid + stride];
            }
            __syncthreads();
        }
        if (tid == 0) {
            float lg0 = l0[0] + b5[0];
            float lg1 = l1[0] + b5[1];
            float z = (lg1 > lg0) ? 1.0f : 0.0f;   // argmax; tie -> class 0
            #pragma unroll
            for (int h = 0; h < H_HEADS; h++)
                out[b * H_HEADS + h] = z;
        }
    }
}

// ---------------- launch --------------------------------------------------------
extern "C" void kernel_launch(void* const* d_in, const int* in_sizes, int n_in,
                              void* d_out, int out_size)
{
    const float* x  = (const float*)d_in[0];
    const int*   cu = (const int*)  d_in[1];
    const float* w1 = (const float*)d_in[2];
    const float* b1 = (const float*)d_in[3];
    const float* w2 = (const float*)d_in[4];
    const float* b2 = (const float*)d_in[5];
    const float* w3 = (const float*)d_in[6];
    const float* b3 = (const float*)d_in[7];
    const float* w4 = (const float*)d_in[8];
    const float* b4 = (const float*)d_in[9];
    const float* w5 = (const float*)d_in[10];
    const float* b5 = (const float*)d_in[11];

    static int smem_set = 0;
    if (!smem_set) {
        cudaFuncSetAttribute(mlp_kernel,
                             cudaFuncAttributeMaxDynamicSharedMemorySize,
                             SM_TOT * 4);
        smem_set = 1;
    }

    reduce_kernel<<<RBLK, 256>>>((const float4*)x, cu);
    mlp_kernel<<<NCTA, NTHR, SM_TOT * 4>>>(cu, w1, b1, w2, b2, w3, b3,
                                           w4, b4, w5, b5, (float*)d_out);
}

// round 12
// speedup vs baseline: 1.1007x; 1.0344x over previous
#include <cuda_runtime.h>
#include <math.h>
#include <stdint.h>

#define T_LEN        32768
#define B_SEG        8
#define H_HEADS      8
#define C_COLS       1024
#define C4           256
#define RBLK         1024
#define ROWS_PER_BLK 32
#define NCTA         16
#define NTHR         512

// ---------------- device scratch (zero-initialized at module load) -----------
__device__ float g_accum[B_SEG * C_COLS];  // segment sums; 0 at entry
__device__ float g_h2[B_SEG * 256];        // L2 partial sums; 0 at entry
__device__ float g_h4[B_SEG * 128];        // L4 partial sums; 0 at entry
__device__ unsigned          g_cnt[4];
__device__ volatile unsigned g_gen[4];

__device__ __forceinline__ float silu(float v) { return v / (1.0f + expf(-v)); }

// PDL controls
__device__ __forceinline__ void gdc_launch_dependents() {
    asm volatile("griddepcontrol.launch_dependents;" ::: "memory");
}
__device__ __forceinline__ void gdc_wait() {
    asm volatile("griddepcontrol.wait;" ::: "memory");
}

// busy-poll grid barrier; generation monotonic across replays
__device__ __forceinline__ void grid_bar(int id, unsigned target)
{
    __syncthreads();
    if (threadIdx.x == 0) {
        __threadfence();
        unsigned gen = g_gen[id];
        if (atomicAdd(&g_cnt[id], 1u) == target - 1u) {
            g_cnt[id] = 0u;
            __threadfence();
            g_gen[id] = gen + 1u;
        } else {
            while (g_gen[id] == gen) { }
            __threadfence();
        }
    }
    __syncthreads();
}

// =================== K1: streaming segment-sum ================================
__global__ void __launch_bounds__(256) reduce_kernel(
    const float4* __restrict__ x4, const int* __restrict__ cu)
{
    gdc_launch_dependents();               // let the MLP start preloading weights

    const int tid = threadIdx.x;
    const int t0  = blockIdx.x * ROWS_PER_BLK;

    __shared__ int scu[B_SEG + 1];
    if (tid <= B_SEG) scu[tid] = cu[tid];
    __syncthreads();

    const int t1 = t0 + ROWS_PER_BLK - 1;
    int s0 = 0; while (s0 < B_SEG - 1 && t0 >= scu[s0 + 1]) s0++;
    int s1 = 0; while (s1 < B_SEG - 1 && t1 >= scu[s1 + 1]) s1++;

    const float4* xp = x4 + (size_t)t0 * C4 + tid;

    if (s0 == s1) {
        float4 a[8];
        #pragma unroll
        for (int i = 0; i < 8; i++) a[i] = make_float4(0.f,0.f,0.f,0.f);
        #pragma unroll
        for (int r = 0; r < ROWS_PER_BLK; r += 8) {
            #pragma unroll
            for (int u = 0; u < 8; u++) {
                float4 v = __ldcs(&xp[(r + u) * C4]);
                a[u].x += v.x; a[u].y += v.y; a[u].z += v.z; a[u].w += v.w;
            }
        }
        #pragma unroll
        for (int s = 4; s > 0; s >>= 1)
            #pragma unroll
            for (int i = 0; i < s; i++) {
                a[i].x += a[i+s].x; a[i].y += a[i+s].y;
                a[i].z += a[i+s].z; a[i].w += a[i+s].w;
            }
        float* dst = g_accum + s0 * C_COLS + tid * 4;
        atomicAdd(dst + 0, a[0].x); atomicAdd(dst + 1, a[0].y);
        atomicAdd(dst + 2, a[0].z); atomicAdd(dst + 3, a[0].w);
    } else {
        float4 a = make_float4(0.f,0.f,0.f,0.f);
        int seg = s0;
        int nxt = (seg < B_SEG - 1) ? scu[seg + 1] : 0x7fffffff;
        for (int r = 0; r < ROWS_PER_BLK; r++) {
            int t = t0 + r;
            if (t >= nxt) {
                float* dst = g_accum + seg * C_COLS + tid * 4;
                atomicAdd(dst + 0, a.x); atomicAdd(dst + 1, a.y);
                atomicAdd(dst + 2, a.z); atomicAdd(dst + 3, a.w);
                a = make_float4(0.f,0.f,0.f,0.f);
                while (seg < B_SEG - 1 && t >= scu[seg + 1]) seg++;
                nxt = (seg < B_SEG - 1) ? scu[seg + 1] : 0x7fffffff;
            }
            float4 v = __ldcs(&xp[r * C4]);
            a.x += v.x; a.y += v.y; a.z += v.z; a.w += v.w;
        }
        float* dst = g_accum + seg * C_COLS + tid * 4;
        atomicAdd(dst + 0, a.x); atomicAdd(dst + 1, a.y);
        atomicAdd(dst + 2, a.z); atomicAdd(dst + 3, a.w);
    }
}

// =================== async-copy helpers =======================================
__device__ __forceinline__ uint32_t smem_u32(const void* p) {
    uint32_t a;
    asm("{ .reg .u64 t; cvta.to.shared.u64 t, %1; cvt.u32.u64 %0, t; }"
        : "=r"(a) : "l"(p));
    return a;
}
__device__ __forceinline__ void cp_async16(uint32_t dst, const void* src) {
    asm volatile("cp.async.cg.shared.global [%0], [%1], 16;"
                 :: "r"(dst), "l"(src) : "memory");
}
__device__ __forceinline__ void cp_commit() {
    asm volatile("cp.async.commit_group;" ::: "memory");
}
template<int N> __device__ __forceinline__ void cp_wait() {
    asm volatile("cp.async.wait_group %0;" :: "n"(N) : "memory");
}

// ---- smem layout (floats) ----------------------------------------------------
#define SM_W1   0
#define SM_W2   8192
#define SM_W3   24576
#define SM_W4   32768
#define SM_XS0  36864
#define SM_XS1  38944
#define SM_RED  39488
#define SM_L0   41536
#define SM_L1V  41664
#define SM_TOT  41792          // floats -> 167,168 bytes

template<int K, int N, int SLICE>
__device__ __forceinline__ void preload_cols(const float* __restrict__ W,
                                             int rank, int tid, uint32_t dst)
{
    constexpr int CROW = SLICE / 4;
    constexpr int CPT  = (K * SLICE / 4) / NTHR;
    const float* wg = W + rank * SLICE;
    #pragma unroll
    for (int c = 0; c < CPT; c++) {
        int chunk = c * NTHR + tid;
        int row   = chunk / CROW;
        int col   = chunk - row * CROW;
        cp_async16(dst + (uint32_t)(row * SLICE + col * 4) * 4u,
                   wg + (size_t)row * N + col * 4);
    }
    cp_commit();
}
template<int FLOATS>
__device__ __forceinline__ void preload_rows(const float* __restrict__ W,
                                             int rank, int tid, uint32_t dst)
{
    constexpr int CPT = (FLOATS / 4) / NTHR;
    const float* wg = W + (size_t)rank * FLOATS;
    #pragma unroll
    for (int c = 0; c < CPT; c++) {
        int chunk = c * NTHR + tid;
        cp_async16(dst + (uint32_t)chunk * 16u, wg + chunk * 4);
    }
    cp_commit();
}

// =================== K2: 2-barrier MLP (PDL secondary) =========================
__global__ void __launch_bounds__(NTHR) mlp_kernel(
    const int* __restrict__ cu,
    const float* __restrict__ w1, const float* __restrict__ b1,
    const float* __restrict__ w2, const float* __restrict__ b2,
    const float* __restrict__ w3, const float* __restrict__ b3,
    const float* __restrict__ w4, const float* __restrict__ b4,
    const float* __restrict__ w5, const float* __restrict__ b5,
    float* __restrict__ out)
{
    extern __shared__ float sm[];
    float*  ws1 = sm + SM_W1;
    float*  ws2 = sm + SM_W2;
    float*  ws3 = sm + SM_W3;
    float*  ws4 = sm + SM_W4;
    float*  xs0 = sm + SM_XS0;
    float*  xs1 = sm + SM_XS1;
    float4* red = (float4*)(sm + SM_RED);
    float*  l0  = sm + SM_L0;
    float*  l1  = sm + SM_L1V;

    const int tid  = threadIdx.x;
    const int rank = blockIdx.x;
    const uint32_t sm0 = smem_u32(sm);

    // ---- weight preload: independent of the reduce — runs UNDER it (PDL) -----
    preload_cols<128, 1024, 64>(w1, rank, tid, sm0 + SM_W1 * 4u);
    preload_rows<64 * 256>     (w2, rank, tid, sm0 + SM_W2 * 4u);
    preload_cols<256,  512, 32>(w3, rank, tid, sm0 + SM_W3 * 4u);
    preload_rows<32 * 128>     (w4, rank, tid, sm0 + SM_W4 * 4u);
    cp_wait<3>();                           // ws1 resident (overlaps reduce)

    // ---- wait for the reduce kernel's results to be visible -------------------
    gdc_wait();

    // ---- pooled mean ----------------------------------------------------------
    #pragma unroll
    for (int c = 0; c < 2; c++) {
        int i = c * NTHR + tid;            // i = b*128 + k
        int k = i & 127, b = i >> 7;
        float s = 0.f;
        #pragma unroll
        for (int h = 0; h < H_HEADS; h++)
            s += __ldcg(&g_accum[b * C_COLS + h * 128 + k]);
        int cnt = cu[b + 1] - cu[b];
        if (cnt < 1) cnt = 1;
        xs0[b * 260 + k] = s / ((float)cnt * (float)H_HEADS);
    }
    __syncthreads();

    // ---- L1: 128 -> [64-slice], silu, LOCAL. 16 j4 x 8 b x 4 ks (k=32) -------
    {
        const int j4 = tid & 15, b = (tid >> 4) & 7, ks = tid >> 7;
        const int k0 = ks * 32;
        float4 acc = make_float4(0.f,0.f,0.f,0.f);
        const float* xb = xs0 + b * 260;
        #pragma unroll 8
        for (int k = k0; k < k0 + 32; k++) {
            float4 w = *(const float4*)&ws1[k * 64 + j4 * 4];
            float  x = xb[k];
            acc.x += x * w.x; acc.y += x * w.y;
            acc.z += x * w.z; acc.w += x * w.w;
        }
        red[(b * 16 + j4) * 4 + ks] = acc;
        __syncthreads();
        if (tid < 128) {
            const int ob = tid >> 4, oj = tid & 15;
            float4 s = make_float4(0.f,0.f,0.f,0.f);
            #pragma unroll
            for (int q = 0; q < 4; q++) {
                float4 v = red[(ob * 16 + oj) * 4 + q];
                s.x += v.x; s.y += v.y; s.z += v.z; s.w += v.w;
            }
            float4 bias = *(const float4*)&b1[rank * 64 + oj * 4];
            float4 o;
            o.x = silu(s.x + bias.x); o.y = silu(s.y + bias.y);
            o.z = silu(s.z + bias.z); o.w = silu(s.w + bias.w);
            *(float4*)&xs1[ob * 68 + oj * 4] = o;
        }
    }
    cp_wait<2>();                           // ws2 resident
    __syncthreads();

    // ---- L2 partial: own 64 k-rows x all 256 j x 8 b -> RED into g_h2 --------
    {
        const int j4 = tid & 63, b = tid >> 6;
        float4 acc = make_float4(0.f,0.f,0.f,0.f);
        const float* xb = xs1 + b * 68;
        #pragma unroll 8
        for (int k = 0; k < 64; k++) {
            float4 w = *(const float4*)&ws2[k * 256 + j4 * 4];
            float  x = xb[k];
            acc.x += x * w.x; acc.y += x * w.y;
            acc.z += x * w.z; acc.w += x * w.w;
        }
        float* dst = &g_h2[b * 256 + j4 * 4];
        atomicAdd(dst + 0, acc.x); atomicAdd(dst + 1, acc.y);
        atomicAdd(dst + 2, acc.z); atomicAdd(dst + 3, acc.w);
    }
    grid_bar(1, NCTA);

    // reset segment accumulator (pooled reads all done before bar1)
    g_accum[rank * 512 + tid] = 0.f;

    // ---- gather h2 (+bias) : one float4 per thread ----------------------------
    {
        const int j4 = tid & 63, b = tid >> 6;
        float4 v = __ldcg((const float4*)&g_h2[b * 256 + j4 * 4]);
        float4 bias = *(const float4*)&b2[j4 * 4];
        v.x += bias.x; v.y += bias.y; v.z += bias.z; v.w += bias.w;
        *(float4*)&xs0[b * 260 + j4 * 4] = v;
    }
    cp_wait<1>();                           // ws3 resident
    __syncthreads();

    // ---- L3: 256 -> [32-slice], silu, LOCAL. 8 j4 x 8 b x 8 ks (k=32) ---------
    {
        const int j4 = tid & 7, b = (tid >> 3) & 7, ks = tid >> 6;
        const int k0 = ks * 32;
        float4 acc = make_float4(0.f,0.f,0.f,0.f);
        const float* xb = xs0 + b * 260;
        #pragma unroll 8
        for (int k = k0; k < k0 + 32; k++) {
            float4 w = *(const float4*)&ws3[k * 32 + j4 * 4];
            float  x = xb[k];
            acc.x += x * w.x; acc.y += x * w.y;
            acc.z += x * w.z; acc.w += x * w.w;
        }
        red[(b * 8 + j4) * 8 + ks] = acc;
        __syncthreads();
        if (tid < 64) {
            const int ob = tid >> 3, oj = tid & 7;
            float4 s = make_float4(0.f,0.f,0.f,0.f);
            #pragma unroll
            for (int q = 0; q < 8; q++) {
                float4 v = red[(ob * 8 + oj) * 8 + q];
                s.x += v.x; s.y += v.y; s.z += v.z; s.w += v.w;
            }
            float4 bias = *(const float4*)&b3[rank * 32 + oj * 4];
            float4 o;
            o.x = silu(s.x + bias.x); o.y = silu(s.y + bias.y);
            o.z = silu(s.z + bias.z); o.w = silu(s.w + bias.w);
            *(float4*)&xs1[ob * 36 + oj * 4] = o;
        }
    }
    cp_wait<0>();                           // ws4 resident
    __syncthreads();

    // ---- L4 partial: own 32 k-rows x all 128 j x 8 b -> RED into g_h4 ---------
    {
        const int j4 = tid & 31, b = (tid >> 5) & 7, ks = tid >> 8;
        const int k0 = ks * 16;
        float4 acc = make_float4(0.f,0.f,0.f,0.f);
        const float* xb = xs1 + b * 36;
        #pragma unroll 8
        for (int k = k0; k < k0 + 16; k++) {
            float4 w = *(const float4*)&ws4[k * 128 + j4 * 4];
            float  x = xb[k];
            acc.x += x * w.x; acc.y += x * w.y;
            acc.z += x * w.z; acc.w += x * w.w;
        }
        red[(b * 32 + j4) * 2 + ks] = acc;
        __syncthreads();
        if (tid < 256) {
            const int ob = tid >> 5, oj = tid & 31;
            float4 s0 = red[(ob * 32 + oj) * 2 + 0];
            float4 s1 = red[(ob * 32 + oj) * 2 + 1];
            float* dst = &g_h4[ob * 128 + oj * 4];
            atomicAdd(dst + 0, s0.x + s1.x); atomicAdd(dst + 1, s0.y + s1.y);
            atomicAdd(dst + 2, s0.z + s1.z); atomicAdd(dst + 3, s0.w + s1.w);
        }
    }
    grid_bar(2, NCTA);

    // reset h2 partials for next replay (all gathers happened before bar2)
    if (tid < 128) g_h2[rank * 128 + tid] = 0.f;
    if (rank >= 8) return;

    // ---- L5: batch = rank. silu(h4)+dot w5, argmax, out, reset ----------------
    {
        const int b = rank;
        if (tid < 128) {
            float v = silu(__ldcg(&g_h4[b * 128 + tid]) + b4[tid]);
            l0[tid] = v * w5[tid * 2 + 0];
            l1[tid] = v * w5[tid * 2 + 1];
            g_h4[b * 128 + tid] = 0.f;        // same-thread reset after read
        }
        __syncthreads();
        #pragma unroll
        for (int stride = 64; stride > 0; stride >>= 1) {
            if (tid < stride) {
                l0[tid] += l0[tid + stride];
                l1[tid] += l1[tid + stride];
            }
            __syncthreads();
        }
        if (tid == 0) {
            float lg0 = l0[0] + b5[0];
            float lg1 = l1[0] + b5[1];
            float z = (lg1 > lg0) ? 1.0f : 0.0f;   // argmax; tie -> class 0
            #pragma unroll
            for (int h = 0; h < H_HEADS; h++)
                out[b * H_HEADS + h] = z;
        }
    }
}

// ---------------- launch --------------------------------------------------------
extern "C" void kernel_launch(void* const* d_in, const int* in_sizes, int n_in,
                              void* d_out, int out_size)
{
    const float* x  = (const float*)d_in[0];
    const int*   cu = (const int*)  d_in[1];
    const float* w1 = (const float*)d_in[2];
    const float* b1 = (const float*)d_in[3];
    const float* w2 = (const float*)d_in[4];
    const float* b2 = (const float*)d_in[5];
    const float* w3 = (const float*)d_in[6];
    const float* b3 = (const float*)d_in[7];
    const float* w4 = (const float*)d_in[8];
    const float* b4 = (const float*)d_in[9];
    const float* w5 = (const float*)d_in[10];
    const float* b5 = (const float*)d_in[11];
    float* outp = (float*)d_out;

    static int smem_set = 0;
    if (!smem_set) {
        cudaFuncSetAttribute(mlp_kernel,
                             cudaFuncAttributeMaxDynamicSharedMemorySize,
                             SM_TOT * 4);
        smem_set = 1;
    }

    reduce_kernel<<<RBLK, 256>>>((const float4*)x, cu);

    // PDL secondary: may start while reduce is running; gdc_wait() inside
    // orders the g_accum reads after reduce completion.
    cudaLaunchConfig_t cfg = {};
    cfg.gridDim         = dim3(NCTA);
    cfg.blockDim        = dim3(NTHR);
    cfg.dynamicSmemBytes = SM_TOT * 4;
    cfg.stream          = 0;
    cudaLaunchAttribute attr[1];
    attr[0].id = cudaLaunchAttributeProgrammaticStreamSerialization;
    attr[0].val.programmaticStreamSerializationAllowed = 1;
    cfg.attrs    = attr;
    cfg.numAttrs = 1;
    cudaLaunchKernelEx(&cfg, mlp_kernel, cu, w1, b1, w2, b2, w3, b3,
                       w4, b4, w5, b5, outp);
}